// round 12
// baseline (speedup 1.0000x reference)
#include <cuda_runtime.h>
#include <cuda_fp16.h>

#define NN 8192
#define FF 128
#define PP 16
#define EMAX 262144

// v16[i] = fp16 concat(nf_i, diff_i)  (256 halves = 512B/row), L2-resident (4MB)
// act-edge value = pa[src]*dot(nf_src,nf_dst) + gg[src]*dot(d_src,d_dst)
__device__ __half g_v[NN * 2 * FF];
__device__ float  g_pa[NN];        // alpha_row
__device__ float  g_gg[NN];        // gamma_row / F
__device__ float  g_nb[NN];        // -beta_row
__device__ int    g_cnt_a[NN], g_cnt_c[NN];      // zero at entry (reset by writer)
__device__ int    g_off_a[NN + 1], g_off_c[NN + 1];
__device__ int    g_cur_a[NN], g_cur_c[NN];
__device__ int    g_dst_a[EMAX], g_dst_c[EMAX];

static __device__ __forceinline__ unsigned h2_bits(__half2 h) {
    return *reinterpret_cast<unsigned*>(&h);
}

// ---------- K1: blocks [0,1024) prep rows; blocks [1024,2048) histogram ----------
__global__ void k1_prep_hist(const float* __restrict__ feature,
                             const float* __restrict__ next_feature,
                             const float* __restrict__ persona_t,
                             const float* __restrict__ alpha,
                             const float* __restrict__ beta,
                             const float* __restrict__ gamma,
                             const int* __restrict__ act_src,
                             const int* __restrict__ edge_src,
                             int E, int Ec) {
    int bid = blockIdx.x;
    if (bid >= 1024) {
        // histogram role
        int t = (bid - 1024) * blockDim.x + threadIdx.x;
        if (t < E)  atomicAdd(&g_cnt_a[__ldg(&act_src[t])], 1);
        if (t < Ec) atomicAdd(&g_cnt_c[__ldg(&edge_src[t])], 1);
        return;
    }
    int row  = bid * 8 + (threadIdx.x >> 5);   // 8192 warps, one row each
    int lane = threadIdx.x & 31;

    const float4* nf4 = (const float4*)(next_feature + (size_t)row * FF);
    const float4* f4  = (const float4*)(feature      + (size_t)row * FF);
    float4 nf = nf4[lane];
    float4 f  = f4[lane];
    float4 d  = make_float4(f.x - nf.x, f.y - nf.y, f.z - nf.z, f.w - nf.w);

    float ss = nf.x*nf.x + nf.y*nf.y + nf.z*nf.z + nf.w*nf.w;
    #pragma unroll
    for (int o = 16; o; o >>= 1) ss += __shfl_xor_sync(0xffffffffu, ss, o);
    float inv = rsqrtf(ss);
    nf.x *= inv; nf.y *= inv; nf.z *= inv; nf.w *= inv;
    float s2 = nf.x*nf.x + nf.y*nf.y + nf.z*nf.z + nf.w*nf.w;
    #pragma unroll
    for (int o = 16; o; o >>= 1) s2 += __shfl_xor_sync(0xffffffffu, s2, o);
    float inv2 = rsqrtf(s2);
    nf.x *= inv2; nf.y *= inv2; nf.z *= inv2; nf.w *= inv2;

    float pa = 0.f, pb = 0.f, pg = 0.f;
    if (lane < PP) {
        float p = persona_t[(size_t)row * PP + lane];
        pa = p * alpha[lane];
        pb = p * beta[lane];
        pg = p * gamma[lane];
    }
    #pragma unroll
    for (int o = 16; o; o >>= 1) {
        pa += __shfl_xor_sync(0xffffffffu, pa, o);
        pb += __shfl_xor_sync(0xffffffffu, pb, o);
        pg += __shfl_xor_sync(0xffffffffu, pg, o);
    }
    if (lane == 0) {
        g_pa[row] = pa;
        g_gg[row] = pg * (1.0f / FF);
        g_nb[row] = -pb;
    }

    uint2* vrow = (uint2*)(g_v + (size_t)row * 2 * FF);
    vrow[lane]      = make_uint2(h2_bits(__floats2half2_rn(nf.x, nf.y)),
                                 h2_bits(__floats2half2_rn(nf.z, nf.w)));
    vrow[32 + lane] = make_uint2(h2_bits(__floats2half2_rn(d.x, d.y)),
                                 h2_bits(__floats2half2_rn(d.z, d.w)));
}

// ---------- K2: exclusive scan of both count arrays (1 block, 256 threads) ----------
static __device__ __forceinline__ void scan_one(const int* __restrict__ cnt,
                                                int* __restrict__ off,
                                                int* __restrict__ cur,
                                                int* wsum) {
    int tid = threadIdx.x;           // 256 threads x 32 elems = 8192
    int lane = tid & 31, wid = tid >> 5;
    int base = tid * 32;
    int local[32];
    int s = 0;
    #pragma unroll
    for (int i = 0; i < 32; i++) { local[i] = s; s += cnt[base + i]; }
    int inc = s;
    #pragma unroll
    for (int o = 1; o < 32; o <<= 1) {
        int t = __shfl_up_sync(0xffffffffu, inc, o);
        if (lane >= o) inc += t;
    }
    int excl = inc - s;
    if (lane == 31) wsum[wid] = inc;
    __syncthreads();
    if (wid == 0 && lane < 8) {
        int v = wsum[lane];
        int in = v;
        #pragma unroll
        for (int o = 1; o < 8; o <<= 1) {
            int t = __shfl_up_sync(0x000000ffu, in, o);
            if (lane >= o) in += t;
        }
        wsum[lane] = in - v;   // exclusive warp offsets
    }
    __syncthreads();
    int tbase = wsum[wid] + excl;
    #pragma unroll
    for (int i = 0; i < 32; i++) {
        int o = tbase + local[i];
        off[base + i] = o;
        cur[base + i] = o;
    }
    if (tid == 255) off[NN] = tbase + s;
}

__global__ void k2_scan() {
    __shared__ int wsum[8];
    scan_one(g_cnt_a, g_off_a, g_cur_a, wsum);
    __syncthreads();
    scan_one(g_cnt_c, g_off_c, g_cur_c, wsum);
}

// ---------- K3: bucket edges by src ----------
__global__ void k3_bucket(const int* __restrict__ act_src,
                          const int* __restrict__ act_dst,
                          const int* __restrict__ edge_src,
                          const int* __restrict__ edge_dst,
                          int E, int Ec) {
    int t = blockIdx.x * blockDim.x + threadIdx.x;
    if (t < E) {
        int s = __ldg(&act_src[t]);
        int p = atomicAdd(&g_cur_a[s], 1);
        g_dst_a[p] = __ldg(&act_dst[t]);
    }
    if (t < Ec) {
        int s = __ldg(&edge_src[t]);
        int p = atomicAdd(&g_cur_c[s], 1);
        g_dst_c[p] = __ldg(&edge_dst[t]);
    }
}

// ---------- K4: block per row — zero row, then add this row's edge values ----------
__global__ void __launch_bounds__(256) k4_write(float* __restrict__ out) {
    int row  = blockIdx.x;
    int tid  = threadIdx.x;
    int lane = tid & 31, wid = tid >> 5;

    // zero the 32KB row (2048 float4, 8 per thread)
    float* outr = out + (size_t)row * NN;
    float4* o4 = (float4*)outr;
    float4 z = make_float4(0.f, 0.f, 0.f, 0.f);
    #pragma unroll
    for (int i = 0; i < 8; i++) o4[tid + i * 256] = z;

    __shared__ float s_pa, s_gg, s_nb;
    if (tid == 0) { s_pa = g_pa[row]; s_gg = g_gg[row]; s_nb = g_nb[row]; }
    __syncthreads();   // zero stores visible before row atomics; scalars ready

    float scale = (lane < 16) ? s_pa : s_gg;

    // each warp holds v[row] in registers (512B loaded once)
    const uint4* vrow = (const uint4*)(g_v + (size_t)row * 2 * FF);
    uint4 ar = vrow[lane];
    float2 a0 = __half22float2(*(__half2*)&ar.x);
    float2 a1 = __half22float2(*(__half2*)&ar.y);
    float2 a2 = __half22float2(*(__half2*)&ar.z);
    float2 a3 = __half22float2(*(__half2*)&ar.w);

    int e0 = g_off_a[row], e1 = g_off_a[row + 1];
    for (int i = e0 + wid; i < e1; i += 8) {
        int dst = g_dst_a[i];
        const uint4* vd = (const uint4*)(g_v + (size_t)dst * 2 * FF);
        uint4 bp = vd[lane];
        float2 b0 = __half22float2(*(__half2*)&bp.x);
        float2 b1 = __half22float2(*(__half2*)&bp.y);
        float2 b2 = __half22float2(*(__half2*)&bp.z);
        float2 b3 = __half22float2(*(__half2*)&bp.w);
        float s;
        s = a0.x * b0.x;
        s = fmaf(a0.y, b0.y, s);
        s = fmaf(a1.x, b1.x, s);
        s = fmaf(a1.y, b1.y, s);
        s = fmaf(a2.x, b2.x, s);
        s = fmaf(a2.y, b2.y, s);
        s = fmaf(a3.x, b3.x, s);
        s = fmaf(a3.y, b3.y, s);
        s *= scale;                      // fp32 per-half scaling (src side)
        #pragma unroll
        for (int o = 16; o; o >>= 1) s += __shfl_xor_sync(0xffffffffu, s, o);
        if (lane == 0) atomicAdd(outr + dst, s);   // row is L2-hot
    }

    int c0 = g_off_c[row], c1 = g_off_c[row + 1];
    for (int i = c0 + tid; i < c1; i += 256)
        atomicAdd(outr + g_dst_c[i], s_nb);

    // restore counters-zero invariant for the next call
    if (tid == 0) { g_cnt_a[row] = 0; g_cnt_c[row] = 0; }
}

extern "C" void kernel_launch(void* const* d_in, const int* in_sizes, int n_in,
                              void* d_out, int out_size) {
    const float* feature      = (const float*)d_in[0];
    const float* next_feature = (const float*)d_in[1];
    const float* persona_t    = (const float*)d_in[2];
    const float* alpha        = (const float*)d_in[3];
    const float* beta         = (const float*)d_in[4];
    const float* gamma        = (const float*)d_in[5];
    const int*   act_src      = (const int*)d_in[6];
    const int*   act_dst      = (const int*)d_in[7];
    const int*   edge_src     = (const int*)d_in[8];
    const int*   edge_dst     = (const int*)d_in[9];
    float* out = (float*)d_out;
    int E  = in_sizes[6];
    int Ec = in_sizes[8];

    int histb = (max(E, Ec) + 255) / 256;            // 1024 for E=262144
    k1_prep_hist<<<1024 + histb, 256>>>(feature, next_feature, persona_t,
                                        alpha, beta, gamma, act_src, edge_src, E, Ec);
    k2_scan<<<1, 256>>>();
    k3_bucket<<<histb, 256>>>(act_src, act_dst, edge_src, edge_dst, E, Ec);
    k4_write<<<NN, 256>>>(out);
}

// round 13
// speedup vs baseline: 1.0591x; 1.0591x over previous
#include <cuda_runtime.h>
#include <cuda_fp16.h>

#define NN 8192
#define FF 128
#define PP 16
#define EMAX 262144
#define CAP 128   // max row degree; Poisson(32) tail => P(overflow) < 1e-40

// v16[i] = fp16 concat(nf_i, diff_i)  (512B/row), L2-resident (4MB)
// act-edge value = pa[src]*dot(nf_src,nf_dst) + gg[src]*dot(d_src,d_dst)
__device__ __half g_v[NN * 2 * FF];
__device__ float  g_pa[NN];                 // alpha_row
__device__ float  g_gg[NN];                 // gamma_row / F
__device__ float  g_nb[NN];                 // -beta_row
__device__ int    g_cnt_a[NN], g_cnt_c[NN]; // zero at entry (reset by k4)
__device__ int    g_dst_a[NN * CAP];        // padded per-row act dst lists
__device__ int    g_dst_c[NN * CAP];        // padded per-row cost dst lists

static __device__ __forceinline__ unsigned h2_bits(__half2 h) {
    return *reinterpret_cast<unsigned*>(&h);
}

// ---- K1: blocks [0,1024) prep rows; blocks [1024,2048) bucket edges ----
__global__ void k1_prep_bucket(const float* __restrict__ feature,
                               const float* __restrict__ next_feature,
                               const float* __restrict__ persona_t,
                               const float* __restrict__ alpha,
                               const float* __restrict__ beta,
                               const float* __restrict__ gamma,
                               const int* __restrict__ act_src,
                               const int* __restrict__ act_dst,
                               const int* __restrict__ edge_src,
                               const int* __restrict__ edge_dst,
                               int E, int Ec) {
    int bid = blockIdx.x;
    if (bid >= 1024) {
        // bucket role: direct scatter into padded rows
        int t = (bid - 1024) * blockDim.x + threadIdx.x;
        if (t < E) {
            int s = __ldg(&act_src[t]);
            int p = atomicAdd(&g_cnt_a[s], 1);
            if (p < CAP) g_dst_a[s * CAP + p] = __ldg(&act_dst[t]);
        }
        if (t < Ec) {
            int s = __ldg(&edge_src[t]);
            int p = atomicAdd(&g_cnt_c[s], 1);
            if (p < CAP) g_dst_c[s * CAP + p] = __ldg(&edge_dst[t]);
        }
        return;
    }
    int row  = bid * 8 + (threadIdx.x >> 5);   // 8192 warps, one row each
    int lane = threadIdx.x & 31;

    const float4* nf4 = (const float4*)(next_feature + (size_t)row * FF);
    const float4* f4  = (const float4*)(feature      + (size_t)row * FF);
    float4 nf = nf4[lane];
    float4 f  = f4[lane];
    float4 d  = make_float4(f.x - nf.x, f.y - nf.y, f.z - nf.z, f.w - nf.w);

    float ss = nf.x*nf.x + nf.y*nf.y + nf.z*nf.z + nf.w*nf.w;
    #pragma unroll
    for (int o = 16; o; o >>= 1) ss += __shfl_xor_sync(0xffffffffu, ss, o);
    float inv = rsqrtf(ss);
    nf.x *= inv; nf.y *= inv; nf.z *= inv; nf.w *= inv;
    float s2 = nf.x*nf.x + nf.y*nf.y + nf.z*nf.z + nf.w*nf.w;
    #pragma unroll
    for (int o = 16; o; o >>= 1) s2 += __shfl_xor_sync(0xffffffffu, s2, o);
    float inv2 = rsqrtf(s2);
    nf.x *= inv2; nf.y *= inv2; nf.z *= inv2; nf.w *= inv2;

    float pa = 0.f, pb = 0.f, pg = 0.f;
    if (lane < PP) {
        float p = persona_t[(size_t)row * PP + lane];
        pa = p * alpha[lane];
        pb = p * beta[lane];
        pg = p * gamma[lane];
    }
    #pragma unroll
    for (int o = 16; o; o >>= 1) {
        pa += __shfl_xor_sync(0xffffffffu, pa, o);
        pb += __shfl_xor_sync(0xffffffffu, pb, o);
        pg += __shfl_xor_sync(0xffffffffu, pg, o);
    }
    if (lane == 0) {
        g_pa[row] = pa;
        g_gg[row] = pg * (1.0f / FF);
        g_nb[row] = -pb;
    }

    uint2* vrow = (uint2*)(g_v + (size_t)row * 2 * FF);
    vrow[lane]      = make_uint2(h2_bits(__floats2half2_rn(nf.x, nf.y)),
                                 h2_bits(__floats2half2_rn(nf.z, nf.w)));
    vrow[32 + lane] = make_uint2(h2_bits(__floats2half2_rn(d.x, d.y)),
                                 h2_bits(__floats2half2_rn(d.z, d.w)));
}

// ---- K4: block per row — zero the row, add this row's edge values, reset cnts ----
__global__ void __launch_bounds__(256) k4_write(float* __restrict__ out) {
    int row  = blockIdx.x;
    int tid  = threadIdx.x;
    int lane = tid & 31, wid = tid >> 5;

    // zero the 32KB row (2048 float4, 8 per thread; fire-and-forget)
    float* outr = out + (size_t)row * NN;
    float4* o4 = (float4*)outr;
    float4 z = make_float4(0.f, 0.f, 0.f, 0.f);
    #pragma unroll
    for (int i = 0; i < 8; i++) o4[tid + i * 256] = z;

    __shared__ float s_pa, s_gg, s_nb;
    __shared__ int   s_na, s_nc;
    if (tid == 0) {
        s_pa = g_pa[row]; s_gg = g_gg[row]; s_nb = g_nb[row];
        int na = g_cnt_a[row]; if (na > CAP) na = CAP;
        int nc = g_cnt_c[row]; if (nc > CAP) nc = CAP;
        s_na = na; s_nc = nc;
        g_cnt_a[row] = 0; g_cnt_c[row] = 0;   // restore invariant
    }
    __syncthreads();

    float scale = (lane < 16) ? s_pa : s_gg;

    // each warp holds v[row] in registers (512B loaded once)
    const uint4* vrow = (const uint4*)(g_v + (size_t)row * 2 * FF);
    uint4 ar = vrow[lane];
    float2 a0 = __half22float2(*(__half2*)&ar.x);
    float2 a1 = __half22float2(*(__half2*)&ar.y);
    float2 a2 = __half22float2(*(__half2*)&ar.z);
    float2 a3 = __half22float2(*(__half2*)&ar.w);

    const int* lst_a = g_dst_a + (size_t)row * CAP;
    for (int i = wid; i < s_na; i += 8) {
        int dst = lst_a[i];
        const uint4* vd = (const uint4*)(g_v + (size_t)dst * 2 * FF);
        uint4 bp = vd[lane];
        float2 b0 = __half22float2(*(__half2*)&bp.x);
        float2 b1 = __half22float2(*(__half2*)&bp.y);
        float2 b2 = __half22float2(*(__half2*)&bp.z);
        float2 b3 = __half22float2(*(__half2*)&bp.w);
        float s;
        s = a0.x * b0.x;
        s = fmaf(a0.y, b0.y, s);
        s = fmaf(a1.x, b1.x, s);
        s = fmaf(a1.y, b1.y, s);
        s = fmaf(a2.x, b2.x, s);
        s = fmaf(a2.y, b2.y, s);
        s = fmaf(a3.x, b3.x, s);
        s = fmaf(a3.y, b3.y, s);
        s *= scale;                       // fp32 per-half scaling (src side)
        #pragma unroll
        for (int o = 16; o; o >>= 1) s += __shfl_xor_sync(0xffffffffu, s, o);
        if (lane == 0) atomicAdd(outr + dst, s);   // row is L2-hot
    }

    const int* lst_c = g_dst_c + (size_t)row * CAP;
    for (int i = tid; i < s_nc; i += 256)
        atomicAdd(outr + lst_c[i], s_nb);
}

extern "C" void kernel_launch(void* const* d_in, const int* in_sizes, int n_in,
                              void* d_out, int out_size) {
    const float* feature      = (const float*)d_in[0];
    const float* next_feature = (const float*)d_in[1];
    const float* persona_t    = (const float*)d_in[2];
    const float* alpha        = (const float*)d_in[3];
    const float* beta         = (const float*)d_in[4];
    const float* gamma        = (const float*)d_in[5];
    const int*   act_src      = (const int*)d_in[6];
    const int*   act_dst      = (const int*)d_in[7];
    const int*   edge_src     = (const int*)d_in[8];
    const int*   edge_dst     = (const int*)d_in[9];
    float* out = (float*)d_out;
    int E  = in_sizes[6];
    int Ec = in_sizes[8];

    int bucketb = (max(E, Ec) + 255) / 256;          // 1024 for E=262144
    k1_prep_bucket<<<1024 + bucketb, 256>>>(feature, next_feature, persona_t,
                                            alpha, beta, gamma,
                                            act_src, act_dst, edge_src, edge_dst,
                                            E, Ec);
    k4_write<<<NN, 256>>>(out);
}

// round 14
// speedup vs baseline: 1.2327x; 1.1640x over previous
#include <cuda_runtime.h>
#include <cuda_fp16.h>

#define NN 8192
#define FF 128
#define PP 16
#define EMAX 262144

// v16[i] = fp16 concat(nf_i, diff_i)  (256 halves = 512B/row), L2-resident (4MB)
// act-edge value = pa[src]*dot(nf_src,nf_dst) + gg[src]*dot(d_src,d_dst)
__device__ __half  g_v[NN * 2 * FF];
__device__ float2  g_pg[NN];      // (alpha_row, gamma_row/F)
__device__ float   g_nb[NN];      // -beta_row
__device__ float   g_val[EMAX];   // per-act-edge values

static __device__ __forceinline__ unsigned h2_bits(__half2 h) {
    return *reinterpret_cast<unsigned*>(&h);
}

// ---------------- prep: warp per row ----------------
__global__ void prep_kernel(const float* __restrict__ feature,
                            const float* __restrict__ next_feature,
                            const float* __restrict__ persona_t,
                            const float* __restrict__ alpha,
                            const float* __restrict__ beta,
                            const float* __restrict__ gamma) {
    int row  = blockIdx.x * 8 + (threadIdx.x >> 5);   // 8192 warps, one row each
    int lane = threadIdx.x & 31;

    const float4* nf4 = (const float4*)(next_feature + (size_t)row * FF);
    const float4* f4  = (const float4*)(feature      + (size_t)row * FF);
    float4 nf = nf4[lane];
    float4 f  = f4[lane];
    float4 d  = make_float4(f.x - nf.x, f.y - nf.y, f.z - nf.z, f.w - nf.w);

    float ss = nf.x*nf.x + nf.y*nf.y + nf.z*nf.z + nf.w*nf.w;
    #pragma unroll
    for (int o = 16; o; o >>= 1) ss += __shfl_xor_sync(0xffffffffu, ss, o);
    float inv = rsqrtf(ss);
    nf.x *= inv; nf.y *= inv; nf.z *= inv; nf.w *= inv;
    float s2 = nf.x*nf.x + nf.y*nf.y + nf.z*nf.z + nf.w*nf.w;
    #pragma unroll
    for (int o = 16; o; o >>= 1) s2 += __shfl_xor_sync(0xffffffffu, s2, o);
    float inv2 = rsqrtf(s2);
    nf.x *= inv2; nf.y *= inv2; nf.z *= inv2; nf.w *= inv2;

    float pa = 0.f, pb = 0.f, pg = 0.f;
    if (lane < PP) {
        float p = persona_t[(size_t)row * PP + lane];
        pa = p * alpha[lane];
        pb = p * beta[lane];
        pg = p * gamma[lane];
    }
    #pragma unroll
    for (int o = 16; o; o >>= 1) {
        pa += __shfl_xor_sync(0xffffffffu, pa, o);
        pb += __shfl_xor_sync(0xffffffffu, pb, o);
        pg += __shfl_xor_sync(0xffffffffu, pg, o);
    }
    if (lane == 0) {
        g_pg[row] = make_float2(pa, pg * (1.0f / FF));
        g_nb[row] = -pb;
    }

    // layout: vrow[0..15] = nf halves, vrow[16..31] = d halves (uint2 granularity: 0..31 | 32..63)
    uint2* vrow = (uint2*)(g_v + (size_t)row * 2 * FF);
    vrow[lane]      = make_uint2(h2_bits(__floats2half2_rn(nf.x, nf.y)),
                                 h2_bits(__floats2half2_rn(nf.z, nf.w)));
    vrow[32 + lane] = make_uint2(h2_bits(__floats2half2_rn(d.x, d.y)),
                                 h2_bits(__floats2half2_rn(d.z, d.w)));
}

// -------- dots: warp per edge, grid-stride, 2-way unrolled --------
static __device__ __forceinline__ float pair_dot(int src, int dst, int lane) {
    const uint4* vs = (const uint4*)(g_v + (size_t)src * 2 * FF);  // 32 x uint4: 0..15 nf, 16..31 d
    const uint4* vd = (const uint4*)(g_v + (size_t)dst * 2 * FF);
    uint4 ap = vs[lane];
    uint4 bp = vd[lane];
    float2 a0 = __half22float2(*(__half2*)&ap.x);
    float2 a1 = __half22float2(*(__half2*)&ap.y);
    float2 a2 = __half22float2(*(__half2*)&ap.z);
    float2 a3 = __half22float2(*(__half2*)&ap.w);
    float2 b0 = __half22float2(*(__half2*)&bp.x);
    float2 b1 = __half22float2(*(__half2*)&bp.y);
    float2 b2 = __half22float2(*(__half2*)&bp.z);
    float2 b3 = __half22float2(*(__half2*)&bp.w);
    float s;
    s = a0.x * b0.x;
    s = fmaf(a0.y, b0.y, s);
    s = fmaf(a1.x, b1.x, s);
    s = fmaf(a1.y, b1.y, s);
    s = fmaf(a2.x, b2.x, s);
    s = fmaf(a2.y, b2.y, s);
    s = fmaf(a3.x, b3.x, s);
    s = fmaf(a3.y, b3.y, s);
    float2 pg = __ldg(&g_pg[src]);
    return s * ((lane < 16) ? pg.x : pg.y);   // fp32 src-side scaling
}

__global__ void dots_kernel(const int* __restrict__ act_src,
                            const int* __restrict__ act_dst, int E) {
    int warp = (blockIdx.x * blockDim.x + threadIdx.x) >> 5;
    int lane = threadIdx.x & 31;
    const int WN = (gridDim.x * blockDim.x) >> 5;
    int e = warp;
    for (; e + WN < E; e += 2 * WN) {
        int s0 = __ldg(&act_src[e]),      d0 = __ldg(&act_dst[e]);
        int s1 = __ldg(&act_src[e + WN]), d1 = __ldg(&act_dst[e + WN]);
        float r0 = pair_dot(s0, d0, lane);
        float r1 = pair_dot(s1, d1, lane);
        #pragma unroll
        for (int o = 16; o; o >>= 1) {
            r0 += __shfl_xor_sync(0xffffffffu, r0, o);
            r1 += __shfl_xor_sync(0xffffffffu, r1, o);
        }
        if (lane == 0) { g_val[e] = r0; g_val[e + WN] = r1; }
    }
    for (; e < E; e += WN) {
        int s0 = __ldg(&act_src[e]), d0 = __ldg(&act_dst[e]);
        float r0 = pair_dot(s0, d0, lane);
        #pragma unroll
        for (int o = 16; o; o >>= 1) r0 += __shfl_xor_sync(0xffffffffu, r0, o);
        if (lane == 0) g_val[e] = r0;
    }
}

// -------- scatter: act values + cost atomics --------
__global__ void scatter_kernel(const int* __restrict__ act_src,
                               const int* __restrict__ act_dst,
                               const int* __restrict__ edge_src,
                               const int* __restrict__ edge_dst,
                               float* __restrict__ out, int E, int Ec) {
    int t = blockIdx.x * blockDim.x + threadIdx.x;
    if (t < E) {
        int src = __ldg(&act_src[t]);
        int dst = __ldg(&act_dst[t]);
        atomicAdd(&out[(size_t)src * NN + dst], g_val[t]);
    } else if (t < E + Ec) {
        int e = t - E;
        int src = __ldg(&edge_src[e]);
        int dst = __ldg(&edge_dst[e]);
        atomicAdd(&out[(size_t)src * NN + dst], g_nb[src]);
    }
}

extern "C" void kernel_launch(void* const* d_in, const int* in_sizes, int n_in,
                              void* d_out, int out_size) {
    const float* feature      = (const float*)d_in[0];
    const float* next_feature = (const float*)d_in[1];
    const float* persona_t    = (const float*)d_in[2];
    const float* alpha        = (const float*)d_in[3];
    const float* beta         = (const float*)d_in[4];
    const float* gamma        = (const float*)d_in[5];
    const int*   act_src      = (const int*)d_in[6];
    const int*   act_dst      = (const int*)d_in[7];
    const int*   edge_src     = (const int*)d_in[8];
    const int*   edge_dst     = (const int*)d_in[9];
    float* out = (float*)d_out;
    int E  = in_sizes[6];
    int Ec = in_sizes[8];

    // lazy one-time handles (host-side only; no device memory)
    static cudaStream_t side = nullptr;
    static cudaEvent_t ev_fork = nullptr, ev_join = nullptr;
    if (!side) {
        cudaStreamCreateWithFlags(&side, cudaStreamNonBlocking);
        cudaEventCreateWithFlags(&ev_fork, cudaEventDisableTiming);
        cudaEventCreateWithFlags(&ev_join, cudaEventDisableTiming);
    }

    // fork: zero-fill (DRAM-store bound) runs parallel to prep+dots (L2-read bound)
    cudaEventRecord(ev_fork, 0);
    cudaStreamWaitEvent(side, ev_fork, 0);
    cudaMemsetAsync(out, 0, (size_t)out_size * sizeof(float), side);
    cudaEventRecord(ev_join, side);

    prep_kernel<<<1024, 256>>>(feature, next_feature, persona_t, alpha, beta, gamma);
    dots_kernel<<<2048, 256>>>(act_src, act_dst, E);

    // join: scatter needs both the zeroed output and the edge values
    cudaStreamWaitEvent(0, ev_join, 0);
    int st = E + Ec;
    scatter_kernel<<<(st + 255) / 256, 256>>>(act_src, act_dst, edge_src, edge_dst,
                                              out, E, Ec);
}